// round 1
// baseline (speedup 1.0000x reference)
#include <cuda_runtime.h>
#include <math.h>

#define BATCH 4
#define NPIX  4096
#define CH    512
#define DQ    64
#define MTOT  (BATCH*NPIX)

// Scratch (device globals: the sanctioned no-alloc workaround)
static __device__ float g_f[BATCH * NPIX * DQ];
static __device__ float g_g[BATCH * NPIX * DQ];
static __device__ float g_v[(size_t)BATCH * NPIX * CH];
static __device__ float g_s[(size_t)BATCH * NPIX * NPIX];   // 256 MB
static __device__ float g_invsum[BATCH * NPIX];

// ---------------------------------------------------------------------------
// Generic 64x64 tiled GEMM: C[M,N] = A[M,K] @ B[K,N], all row-major fp32.
// 16x16 threads, each computes a 4x4 micro-tile. K-tile = 32.
// ---------------------------------------------------------------------------
__global__ __launch_bounds__(256)
void gemm_proj(const float* __restrict__ A, const float* __restrict__ B,
               float* __restrict__ C, int M, int N, int K)
{
    __shared__ float As[64][33];
    __shared__ float Bs[32][64];

    const int tx = threadIdx.x, ty = threadIdx.y;
    const int tid = ty * 16 + tx;
    const int bm = blockIdx.y * 64;
    const int bn = blockIdx.x * 64;

    float acc[4][4] = {};

    for (int k0 = 0; k0 < K; k0 += 32) {
        #pragma unroll
        for (int l = 0; l < 8; l++) {
            int idx = tid + l * 256;
            int r = idx >> 5, c = idx & 31;
            As[r][c] = A[(size_t)(bm + r) * K + k0 + c];
        }
        #pragma unroll
        for (int l = 0; l < 8; l++) {
            int idx = tid + l * 256;
            int r = idx >> 6, c = idx & 63;
            Bs[r][c] = B[(size_t)(k0 + r) * N + bn + c];
        }
        __syncthreads();

        #pragma unroll
        for (int kk = 0; kk < 32; kk++) {
            float a[4], b[4];
            #pragma unroll
            for (int i = 0; i < 4; i++) a[i] = As[ty * 4 + i][kk];
            #pragma unroll
            for (int j = 0; j < 4; j++) b[j] = Bs[kk][tx * 4 + j];
            #pragma unroll
            for (int i = 0; i < 4; i++)
                #pragma unroll
                for (int j = 0; j < 4; j++)
                    acc[i][j] += a[i] * b[j];
        }
        __syncthreads();
    }

    #pragma unroll
    for (int i = 0; i < 4; i++)
        #pragma unroll
        for (int j = 0; j < 4; j++)
            C[(size_t)(bm + ty * 4 + i) * N + bn + tx * 4 + j] = acc[i][j];
}

// ---------------------------------------------------------------------------
// S = F @ G^T per batch. F,G: [NPIX, DQ] row-major. S: [NPIX, NPIX].
// ---------------------------------------------------------------------------
__global__ __launch_bounds__(256)
void gemm_s()
{
    __shared__ float Fs[64][33];
    __shared__ float Gs[64][33];

    const int tx = threadIdx.x, ty = threadIdx.y;
    const int tid = ty * 16 + tx;
    const int bm = blockIdx.y * 64;   // query rows
    const int bn = blockIdx.x * 64;   // key rows
    const int b  = blockIdx.z;

    const float* F = g_f + (size_t)b * NPIX * DQ;
    const float* G = g_g + (size_t)b * NPIX * DQ;
    float* S = g_s + (size_t)b * NPIX * NPIX;

    float acc[4][4] = {};

    for (int k0 = 0; k0 < DQ; k0 += 32) {
        #pragma unroll
        for (int l = 0; l < 8; l++) {
            int idx = tid + l * 256;
            int r = idx >> 5, c = idx & 31;
            Fs[r][c] = F[(bm + r) * DQ + k0 + c];
            Gs[r][c] = G[(bn + r) * DQ + k0 + c];
        }
        __syncthreads();

        #pragma unroll
        for (int kk = 0; kk < 32; kk++) {
            float a[4], bb[4];
            #pragma unroll
            for (int i = 0; i < 4; i++) a[i]  = Fs[ty * 4 + i][kk];
            #pragma unroll
            for (int j = 0; j < 4; j++) bb[j] = Gs[tx * 4 + j][kk];
            #pragma unroll
            for (int i = 0; i < 4; i++)
                #pragma unroll
                for (int j = 0; j < 4; j++)
                    acc[i][j] += a[i] * bb[j];
        }
        __syncthreads();
    }

    #pragma unroll
    for (int i = 0; i < 4; i++)
        #pragma unroll
        for (int j = 0; j < 4; j++)
            S[(size_t)(bm + ty * 4 + i) * NPIX + bn + tx * 4 + j] = acc[i][j];
}

// ---------------------------------------------------------------------------
// Row softmax over S: writes back UNNORMALIZED exp(s - rowmax); stores 1/sum.
// One 256-thread block per row. float4 vectorized.
// ---------------------------------------------------------------------------
__global__ __launch_bounds__(256)
void softmax_rows()
{
    const int row = blockIdx.x;
    const int b   = blockIdx.y;
    float* p = g_s + ((size_t)b * NPIX + row) * NPIX;
    float4* p4 = reinterpret_cast<float4*>(p);
    const int tid = threadIdx.x;

    __shared__ float red[8];

    // pass 1: row max
    float m = -1e30f;
    for (int i = tid; i < NPIX / 4; i += 256) {
        float4 t = p4[i];
        m = fmaxf(m, fmaxf(fmaxf(t.x, t.y), fmaxf(t.z, t.w)));
    }
    #pragma unroll
    for (int o = 16; o; o >>= 1) m = fmaxf(m, __shfl_xor_sync(0xFFFFFFFFu, m, o));
    if ((tid & 31) == 0) red[tid >> 5] = m;
    __syncthreads();
    if (tid < 32) {
        float v = (tid < 8) ? red[tid] : -1e30f;
        #pragma unroll
        for (int o = 4; o; o >>= 1) v = fmaxf(v, __shfl_xor_sync(0xFFFFFFFFu, v, o));
        if (tid == 0) red[0] = v;
    }
    __syncthreads();
    m = red[0];
    __syncthreads();

    // pass 2: exp + sum (write back unnormalized)
    const float LOG2E = 1.4426950408889634f;
    float sum = 0.0f;
    for (int i = tid; i < NPIX / 4; i += 256) {
        float4 t = p4[i];
        t.x = exp2f((t.x - m) * LOG2E);
        t.y = exp2f((t.y - m) * LOG2E);
        t.z = exp2f((t.z - m) * LOG2E);
        t.w = exp2f((t.w - m) * LOG2E);
        p4[i] = t;
        sum += t.x + t.y + t.z + t.w;
    }
    #pragma unroll
    for (int o = 16; o; o >>= 1) sum += __shfl_xor_sync(0xFFFFFFFFu, sum, o);
    if ((tid & 31) == 0) red[tid >> 5] = sum;
    __syncthreads();
    if (tid < 32) {
        float v = (tid < 8) ? red[tid] : 0.0f;
        #pragma unroll
        for (int o = 4; o; o >>= 1) v += __shfl_xor_sync(0xFFFFFFFFu, v, o);
        if (tid == 0) g_invsum[b * NPIX + row] = 1.0f / v;
    }
}

// ---------------------------------------------------------------------------
// O = P @ V with epilogue: out = gamma * (acc * invsum[row]) + x
// A = unnormalized exp(S) [NPIX, NPIX], B = V [NPIX, CH].
// ---------------------------------------------------------------------------
__global__ __launch_bounds__(256)
void gemm_pv(const float* __restrict__ x, const float* __restrict__ gamma,
             float* __restrict__ out)
{
    __shared__ float As[64][33];
    __shared__ float Bs[32][64];

    const int tx = threadIdx.x, ty = threadIdx.y;
    const int tid = ty * 16 + tx;
    const int bm = blockIdx.y * 64;   // query rows
    const int bn = blockIdx.x * 64;   // V columns
    const int b  = blockIdx.z;

    const float* S = g_s + (size_t)b * NPIX * NPIX;
    const float* V = g_v + (size_t)b * NPIX * CH;

    float acc[4][4] = {};

    for (int k0 = 0; k0 < NPIX; k0 += 32) {
        #pragma unroll
        for (int l = 0; l < 8; l++) {
            int idx = tid + l * 256;
            int r = idx >> 5, c = idx & 31;
            As[r][c] = S[(size_t)(bm + r) * NPIX + k0 + c];
        }
        #pragma unroll
        for (int l = 0; l < 8; l++) {
            int idx = tid + l * 256;
            int r = idx >> 6, c = idx & 63;
            Bs[r][c] = V[(size_t)(k0 + r) * CH + bn + c];
        }
        __syncthreads();

        #pragma unroll
        for (int kk = 0; kk < 32; kk++) {
            float a[4], bb[4];
            #pragma unroll
            for (int i = 0; i < 4; i++) a[i]  = As[ty * 4 + i][kk];
            #pragma unroll
            for (int j = 0; j < 4; j++) bb[j] = Bs[kk][tx * 4 + j];
            #pragma unroll
            for (int i = 0; i < 4; i++)
                #pragma unroll
                for (int j = 0; j < 4; j++)
                    acc[i][j] += a[i] * bb[j];
        }
        __syncthreads();
    }

    const float gam = gamma[0];
    float inv[4];
    #pragma unroll
    for (int i = 0; i < 4; i++) inv[i] = g_invsum[b * NPIX + bm + ty * 4 + i];

    #pragma unroll
    for (int i = 0; i < 4; i++)
        #pragma unroll
        for (int j = 0; j < 4; j++) {
            size_t idx = ((size_t)b * NPIX + bm + ty * 4 + i) * CH + bn + tx * 4 + j;
            out[idx] = gam * (acc[i][j] * inv[i]) + x[idx];
        }
}

// ---------------------------------------------------------------------------
extern "C" void kernel_launch(void* const* d_in, const int* in_sizes, int n_in,
                              void* d_out, int out_size)
{
    const float* x     = (const float*)d_in[0];
    const float* wf    = (const float*)d_in[1];
    const float* wg    = (const float*)d_in[2];
    const float* wh    = (const float*)d_in[3];
    const float* gamma = (const float*)d_in[4];
    float* out = (float*)d_out;

    float *pf, *pg, *pv;
    cudaGetSymbolAddress((void**)&pf, g_f);
    cudaGetSymbolAddress((void**)&pg, g_g);
    cudaGetSymbolAddress((void**)&pv, g_v);

    dim3 th(16, 16);

    // Projections: f, g, v
    gemm_proj<<<dim3(1, MTOT / 64), th>>>(x, wf, pf, MTOT, DQ, CH);
    gemm_proj<<<dim3(1, MTOT / 64), th>>>(x, wg, pg, MTOT, DQ, CH);
    gemm_proj<<<dim3(CH / 64, MTOT / 64), th>>>(x, wh, pv, MTOT, CH, CH);

    // S = f @ g^T
    gemm_s<<<dim3(NPIX / 64, NPIX / 64, BATCH), th>>>();

    // softmax (unnormalized exp + invsum)
    softmax_rows<<<dim3(NPIX, BATCH), 256>>>();

    // O = P @ V, fused normalize + gamma + residual
    gemm_pv<<<dim3(CH / 64, NPIX / 64, BATCH), th>>>(x, gamma, out);
}

// round 2
// speedup vs baseline: 1.2111x; 1.2111x over previous
#include <cuda_runtime.h>
#include <mma.h>
#include <math.h>

using namespace nvcuda;

#define BATCH 4
#define NPIX  4096
#define CH    512
#define DQ    64
#define MTOT  (BATCH*NPIX)

// Scratch (device globals: the sanctioned no-alloc workaround)
static __device__ float g_f[BATCH * NPIX * DQ];
static __device__ float g_g[BATCH * NPIX * DQ];
static __device__ float g_v[(size_t)BATCH * NPIX * CH];
static __device__ float g_s[(size_t)BATCH * NPIX * NPIX];   // 256 MB

// ---------------------------------------------------------------------------
// FFMA GEMM for the small f/g projections (N=64): C = A[M,K] @ B[K,64]
// ---------------------------------------------------------------------------
__global__ __launch_bounds__(256)
void gemm_proj(const float* __restrict__ A, const float* __restrict__ B,
               float* __restrict__ C, int M, int N, int K)
{
    __shared__ float As[64][33];
    __shared__ float Bs[32][64];

    const int tx = threadIdx.x, ty = threadIdx.y;
    const int tid = ty * 16 + tx;
    const int bm = blockIdx.y * 64;
    const int bn = blockIdx.x * 64;

    float acc[4][4] = {};

    for (int k0 = 0; k0 < K; k0 += 32) {
        #pragma unroll
        for (int l = 0; l < 8; l++) {
            int idx = tid + l * 256;
            int r = idx >> 5, c = idx & 31;
            As[r][c] = A[(size_t)(bm + r) * K + k0 + c];
        }
        #pragma unroll
        for (int l = 0; l < 8; l++) {
            int idx = tid + l * 256;
            int r = idx >> 6, c = idx & 63;
            Bs[r][c] = B[(size_t)(k0 + r) * N + bn + c];
        }
        __syncthreads();

        #pragma unroll
        for (int kk = 0; kk < 32; kk++) {
            float a[4], b[4];
            #pragma unroll
            for (int i = 0; i < 4; i++) a[i] = As[ty * 4 + i][kk];
            #pragma unroll
            for (int j = 0; j < 4; j++) b[j] = Bs[kk][tx * 4 + j];
            #pragma unroll
            for (int i = 0; i < 4; i++)
                #pragma unroll
                for (int j = 0; j < 4; j++)
                    acc[i][j] += a[i] * b[j];
        }
        __syncthreads();
    }

    #pragma unroll
    for (int i = 0; i < 4; i++)
        #pragma unroll
        for (int j = 0; j < 4; j++)
            C[(size_t)(bm + ty * 4 + i) * N + bn + tx * 4 + j] = acc[i][j];
}

// ---------------------------------------------------------------------------
// TF32 tensor-core GEMM: C[M,N](+z*cStride) = A[M,K] @ B or B^T
//   Block tile 128x128, K-tile 32, 8 warps (2x4), warp tile 64x32.
//   TRANSB:  B is [N,K] row-major (consumed as B^T via col_major fragments)
//   EPI_RES: C = gamma * acc + x   (x same layout/stride as C)
// ---------------------------------------------------------------------------
template<bool TRANSB, bool EPI_RES>
__global__ __launch_bounds__(256)
void gemm_tf32(const float* __restrict__ A, int lda, size_t aStride,
               const float* __restrict__ B, int ldb, size_t bStride,
               float* __restrict__ C, int ldc, size_t cStride,
               int K,
               const float* __restrict__ xres, const float* __restrict__ gam_p)
{
    __shared__ float As[128][36];      // 128 x 32 (+pad)
    __shared__ float Bs[4608];         // TRANSB: [128][36]  else: [32][132]

    const int tid  = threadIdx.x;
    const int warp = tid >> 5;
    const int wm   = warp >> 2;        // 0..1 -> row offset wm*64
    const int wn   = warp & 3;         // 0..3 -> col offset wn*32
    const int bm   = blockIdx.y * 128;
    const int bn   = blockIdx.x * 128;

    const float* Ab = A + blockIdx.z * aStride;
    const float* Bb = B + blockIdx.z * bStride;

    wmma::fragment<wmma::accumulator, 16, 16, 8, float> acc[4][2];
    #pragma unroll
    for (int mi = 0; mi < 4; mi++)
        #pragma unroll
        for (int ni = 0; ni < 2; ni++)
            wmma::fill_fragment(acc[mi][ni], 0.0f);

    for (int k0 = 0; k0 < K; k0 += 32) {
        // Load A tile 128x32 (float4)
        #pragma unroll
        for (int l = 0; l < 4; l++) {
            int i = tid + l * 256;
            int r = i >> 3, c4 = i & 7;
            const float4 t = *reinterpret_cast<const float4*>(
                &Ab[(size_t)(bm + r) * lda + k0 + c4 * 4]);
            *reinterpret_cast<float4*>(&As[r][c4 * 4]) = t;
        }
        // Load B tile
        if (TRANSB) {
            // B[N,K] row-major -> Bs[n][k], stride 36
            #pragma unroll
            for (int l = 0; l < 4; l++) {
                int i = tid + l * 256;
                int r = i >> 3, c4 = i & 7;
                const float4 t = *reinterpret_cast<const float4*>(
                    &Bb[(size_t)(bn + r) * ldb + k0 + c4 * 4]);
                *reinterpret_cast<float4*>(&Bs[r * 36 + c4 * 4]) = t;
            }
        } else {
            // B[K,N] row-major -> Bs[k][n], stride 132
            #pragma unroll
            for (int l = 0; l < 4; l++) {
                int i = tid + l * 256;
                int r = i >> 5, c4 = i & 31;
                const float4 t = *reinterpret_cast<const float4*>(
                    &Bb[(size_t)(k0 + r) * ldb + bn + c4 * 4]);
                *reinterpret_cast<float4*>(&Bs[r * 132 + c4 * 4]) = t;
            }
        }
        __syncthreads();

        #pragma unroll
        for (int kk = 0; kk < 32; kk += 8) {
            wmma::fragment<wmma::matrix_a, 16, 16, 8, wmma::precision::tf32,
                           wmma::row_major> af[4];
            #pragma unroll
            for (int mi = 0; mi < 4; mi++) {
                wmma::load_matrix_sync(af[mi], &As[wm * 64 + mi * 16][kk], 36);
                #pragma unroll
                for (int e = 0; e < af[mi].num_elements; e++)
                    af[mi].x[e] = wmma::__float_to_tf32(af[mi].x[e]);
            }
            if (TRANSB) {
                wmma::fragment<wmma::matrix_b, 16, 16, 8, wmma::precision::tf32,
                               wmma::col_major> bf[2];
                #pragma unroll
                for (int ni = 0; ni < 2; ni++) {
                    wmma::load_matrix_sync(bf[ni], &Bs[(wn * 32 + ni * 16) * 36 + kk], 36);
                    #pragma unroll
                    for (int e = 0; e < bf[ni].num_elements; e++)
                        bf[ni].x[e] = wmma::__float_to_tf32(bf[ni].x[e]);
                }
                #pragma unroll
                for (int mi = 0; mi < 4; mi++)
                    #pragma unroll
                    for (int ni = 0; ni < 2; ni++)
                        wmma::mma_sync(acc[mi][ni], af[mi], bf[ni], acc[mi][ni]);
            } else {
                wmma::fragment<wmma::matrix_b, 16, 16, 8, wmma::precision::tf32,
                               wmma::row_major> bf[2];
                #pragma unroll
                for (int ni = 0; ni < 2; ni++) {
                    wmma::load_matrix_sync(bf[ni], &Bs[kk * 132 + wn * 32 + ni * 16], 132);
                    #pragma unroll
                    for (int e = 0; e < bf[ni].num_elements; e++)
                        bf[ni].x[e] = wmma::__float_to_tf32(bf[ni].x[e]);
                }
                #pragma unroll
                for (int mi = 0; mi < 4; mi++)
                    #pragma unroll
                    for (int ni = 0; ni < 2; ni++)
                        wmma::mma_sync(acc[mi][ni], af[mi], bf[ni], acc[mi][ni]);
            }
        }
        __syncthreads();
    }

    // Epilogue
    float* Cb = C + blockIdx.z * cStride;
    const float gam = EPI_RES ? gam_p[0] : 0.0f;

    #pragma unroll
    for (int mi = 0; mi < 4; mi++) {
        #pragma unroll
        for (int ni = 0; ni < 2; ni++) {
            const int row = bm + wm * 64 + mi * 16;
            const int col = bn + wn * 32 + ni * 16;
            float* cp = Cb + (size_t)row * ldc + col;
            if (EPI_RES) {
                wmma::fragment<wmma::accumulator, 16, 16, 8, float> xf;
                const float* xp = xres + blockIdx.z * cStride + (size_t)row * ldc + col;
                wmma::load_matrix_sync(xf, xp, ldc, wmma::mem_row_major);
                #pragma unroll
                for (int e = 0; e < xf.num_elements; e++)
                    acc[mi][ni].x[e] = gam * acc[mi][ni].x[e] + xf.x[e];
            }
            wmma::store_matrix_sync(cp, acc[mi][ni], ldc, wmma::mem_row_major);
        }
    }
}

// ---------------------------------------------------------------------------
// Register-resident row softmax: one read, one normalized write.
// 256 threads/row; each thread holds 16 values (4 float4).
// ---------------------------------------------------------------------------
__global__ __launch_bounds__(256)
void softmax_rows()
{
    const int row = blockIdx.x;
    const int b   = blockIdx.y;
    float4* p4 = reinterpret_cast<float4*>(
        g_s + ((size_t)b * NPIX + row) * NPIX);
    const int tid = threadIdx.x;

    __shared__ float red[8];

    float4 v[4];
    #pragma unroll
    for (int j = 0; j < 4; j++) v[j] = p4[tid + j * 256];

    // row max
    float m = -1e30f;
    #pragma unroll
    for (int j = 0; j < 4; j++)
        m = fmaxf(m, fmaxf(fmaxf(v[j].x, v[j].y), fmaxf(v[j].z, v[j].w)));
    #pragma unroll
    for (int o = 16; o; o >>= 1) m = fmaxf(m, __shfl_xor_sync(0xFFFFFFFFu, m, o));
    if ((tid & 31) == 0) red[tid >> 5] = m;
    __syncthreads();
    {
        float t = red[tid & 7];
        #pragma unroll
        for (int o = 4; o; o >>= 1) t = fmaxf(t, __shfl_xor_sync(0xFFFFFFFFu, t, o));
        m = t;
    }
    __syncthreads();

    // exp in registers + sum
    const float LOG2E = 1.4426950408889634f;
    float sum = 0.0f;
    #pragma unroll
    for (int j = 0; j < 4; j++) {
        v[j].x = exp2f((v[j].x - m) * LOG2E);
        v[j].y = exp2f((v[j].y - m) * LOG2E);
        v[j].z = exp2f((v[j].z - m) * LOG2E);
        v[j].w = exp2f((v[j].w - m) * LOG2E);
        sum += v[j].x + v[j].y + v[j].z + v[j].w;
    }
    #pragma unroll
    for (int o = 16; o; o >>= 1) sum += __shfl_xor_sync(0xFFFFFFFFu, sum, o);
    if ((tid & 31) == 0) red[tid >> 5] = sum;
    __syncthreads();
    {
        float t = red[tid & 7];
        #pragma unroll
        for (int o = 4; o; o >>= 1) t += __shfl_xor_sync(0xFFFFFFFFu, t, o);
        sum = t;
    }
    const float inv = 1.0f / sum;

    // normalized write
    #pragma unroll
    for (int j = 0; j < 4; j++) {
        v[j].x *= inv; v[j].y *= inv; v[j].z *= inv; v[j].w *= inv;
        p4[tid + j * 256] = v[j];
    }
}

// ---------------------------------------------------------------------------
extern "C" void kernel_launch(void* const* d_in, const int* in_sizes, int n_in,
                              void* d_out, int out_size)
{
    const float* x     = (const float*)d_in[0];
    const float* wf    = (const float*)d_in[1];
    const float* wg    = (const float*)d_in[2];
    const float* wh    = (const float*)d_in[3];
    const float* gamma = (const float*)d_in[4];
    float* out = (float*)d_out;

    float *pf, *pg, *pv, *ps;
    cudaGetSymbolAddress((void**)&pf, g_f);
    cudaGetSymbolAddress((void**)&pg, g_g);
    cudaGetSymbolAddress((void**)&pv, g_v);
    cudaGetSymbolAddress((void**)&ps, g_s);

    // f, g projections (small; FFMA path)
    gemm_proj<<<dim3(1, MTOT / 64), dim3(16, 16)>>>(x, wf, pf, MTOT, DQ, CH);
    gemm_proj<<<dim3(1, MTOT / 64), dim3(16, 16)>>>(x, wg, pg, MTOT, DQ, CH);

    // v = x @ Wh   [16384,512] = [16384,512]@[512,512]
    gemm_tf32<false, false><<<dim3(CH / 128, MTOT / 128, 1), 256>>>(
        x, CH, 0, wh, CH, 0, pv, CH, 0, CH, nullptr, nullptr);

    // S = f @ g^T  per batch  [4096,4096]
    gemm_tf32<true, false><<<dim3(NPIX / 128, NPIX / 128, BATCH), 256>>>(
        pf, DQ, (size_t)NPIX * DQ,
        pg, DQ, (size_t)NPIX * DQ,
        ps, NPIX, (size_t)NPIX * NPIX,
        DQ, nullptr, nullptr);

    // row softmax (normalized, in place)
    softmax_rows<<<dim3(NPIX, BATCH), 256>>>();

    // out = gamma * (P @ V) + x   per batch
    gemm_tf32<false, true><<<dim3(CH / 128, NPIX / 128, BATCH), 256>>>(
        ps, NPIX, (size_t)NPIX * NPIX,
        pv, CH, (size_t)NPIX * CH,
        out, CH, (size_t)NPIX * CH,
        NPIX, x, gamma);
}

// round 4
// speedup vs baseline: 1.6508x; 1.3630x over previous
#include <cuda_runtime.h>
#include <mma.h>
#include <math.h>
#include <stdint.h>

using namespace nvcuda;

#define BATCH 4
#define NPIX  4096
#define CH    512
#define DQ    64
#define MTOT  (BATCH*NPIX)

// Scratch (device globals: the sanctioned no-alloc workaround)
static __device__ float g_f[BATCH * NPIX * DQ];
static __device__ float g_g[BATCH * NPIX * DQ];
static __device__ float g_v[(size_t)BATCH * NPIX * CH];
static __device__ float g_s[(size_t)BATCH * NPIX * NPIX];   // 256 MB, holds exp(S)

// ---------------------------------------------------------------------------
// cp.async helpers
// ---------------------------------------------------------------------------
__device__ __forceinline__ void cp_async16(void* smem_dst, const void* gmem_src) {
    uint32_t sa = (uint32_t)__cvta_generic_to_shared(smem_dst);
    asm volatile("cp.async.cg.shared.global [%0], [%1], 16;\n" :: "r"(sa), "l"(gmem_src));
}
__device__ __forceinline__ void cp_commit() {
    asm volatile("cp.async.commit_group;\n");
}
__device__ __forceinline__ void cp_wait_all() {
    asm volatile("cp.async.wait_group 0;\n");
}

// ---------------------------------------------------------------------------
// FFMA GEMM for the small f/g projections (N=64): C = A[M,K] @ B[K,64]
// ---------------------------------------------------------------------------
__global__ __launch_bounds__(256)
void gemm_proj(const float* __restrict__ A, const float* __restrict__ B,
               float* __restrict__ C, int M, int N, int K)
{
    __shared__ float As[64][33];
    __shared__ float Bs[32][64];

    const int tx = threadIdx.x, ty = threadIdx.y;
    const int tid = ty * 16 + tx;
    const int bm = blockIdx.y * 64;
    const int bn = blockIdx.x * 64;

    float acc[4][4] = {};

    for (int k0 = 0; k0 < K; k0 += 32) {
        #pragma unroll
        for (int l = 0; l < 8; l++) {
            int idx = tid + l * 256;
            int r = idx >> 5, c = idx & 31;
            As[r][c] = A[(size_t)(bm + r) * K + k0 + c];
        }
        #pragma unroll
        for (int l = 0; l < 8; l++) {
            int idx = tid + l * 256;
            int r = idx >> 6, c = idx & 63;
            Bs[r][c] = B[(size_t)(k0 + r) * N + bn + c];
        }
        __syncthreads();

        #pragma unroll
        for (int kk = 0; kk < 32; kk++) {
            float a[4], b[4];
            #pragma unroll
            for (int i = 0; i < 4; i++) a[i] = As[ty * 4 + i][kk];
            #pragma unroll
            for (int j = 0; j < 4; j++) b[j] = Bs[kk][tx * 4 + j];
            #pragma unroll
            for (int i = 0; i < 4; i++)
                #pragma unroll
                for (int j = 0; j < 4; j++)
                    acc[i][j] += a[i] * b[j];
        }
        __syncthreads();
    }

    #pragma unroll
    for (int i = 0; i < 4; i++)
        #pragma unroll
        for (int j = 0; j < 4; j++)
            C[(size_t)(bm + ty * 4 + i) * N + bn + tx * 4 + j] = acc[i][j];
}

// ---------------------------------------------------------------------------
// v = x @ Wh : TF32 GEMM, 128x128 tile, K-tile 32.
// ---------------------------------------------------------------------------
__global__ __launch_bounds__(256)
void gemm_v(const float* __restrict__ A, const float* __restrict__ B,
            float* __restrict__ C)
{
    __shared__ float As[128][36];
    __shared__ float Bs[32][132];

    const int tid  = threadIdx.x;
    const int warp = tid >> 5;
    const int wm   = warp >> 2;
    const int wn   = warp & 3;
    const int bm   = blockIdx.y * 128;
    const int bn   = blockIdx.x * 128;

    wmma::fragment<wmma::accumulator, 16, 16, 8, float> acc[4][2];
    #pragma unroll
    for (int mi = 0; mi < 4; mi++)
        #pragma unroll
        for (int ni = 0; ni < 2; ni++)
            wmma::fill_fragment(acc[mi][ni], 0.0f);

    for (int k0 = 0; k0 < CH; k0 += 32) {
        #pragma unroll
        for (int l = 0; l < 4; l++) {
            int i = tid + l * 256;
            int r = i >> 3, c4 = i & 7;
            *reinterpret_cast<float4*>(&As[r][c4 * 4]) =
                *reinterpret_cast<const float4*>(&A[(size_t)(bm + r) * CH + k0 + c4 * 4]);
        }
        #pragma unroll
        for (int l = 0; l < 4; l++) {
            int i = tid + l * 256;
            int r = i >> 5, c4 = i & 31;
            *reinterpret_cast<float4*>(&Bs[r][c4 * 4]) =
                *reinterpret_cast<const float4*>(&B[(size_t)(k0 + r) * CH + bn + c4 * 4]);
        }
        __syncthreads();

        #pragma unroll
        for (int kk = 0; kk < 32; kk += 8) {
            wmma::fragment<wmma::matrix_a, 16, 16, 8, wmma::precision::tf32, wmma::row_major> af[4];
            wmma::fragment<wmma::matrix_b, 16, 16, 8, wmma::precision::tf32, wmma::row_major> bf[2];
            #pragma unroll
            for (int mi = 0; mi < 4; mi++) {
                wmma::load_matrix_sync(af[mi], &As[wm * 64 + mi * 16][kk], 36);
                #pragma unroll
                for (int e = 0; e < af[mi].num_elements; e++)
                    af[mi].x[e] = wmma::__float_to_tf32(af[mi].x[e]);
            }
            #pragma unroll
            for (int ni = 0; ni < 2; ni++) {
                wmma::load_matrix_sync(bf[ni], &Bs[kk][wn * 32 + ni * 16], 132);
                #pragma unroll
                for (int e = 0; e < bf[ni].num_elements; e++)
                    bf[ni].x[e] = wmma::__float_to_tf32(bf[ni].x[e]);
            }
            #pragma unroll
            for (int mi = 0; mi < 4; mi++)
                #pragma unroll
                for (int ni = 0; ni < 2; ni++)
                    wmma::mma_sync(acc[mi][ni], af[mi], bf[ni], acc[mi][ni]);
        }
        __syncthreads();
    }

    #pragma unroll
    for (int mi = 0; mi < 4; mi++)
        #pragma unroll
        for (int ni = 0; ni < 2; ni++)
            wmma::store_matrix_sync(
                &C[(size_t)(bm + wm * 64 + mi * 16) * CH + bn + wn * 32 + ni * 16],
                acc[mi][ni], CH, wmma::mem_row_major);
}

// ---------------------------------------------------------------------------
// exp(S) = exp(f @ g^T), per batch. 128x128 tile, single K=64 pass.
// Writes UNNORMALIZED exp(s) (softmax is shift-invariant; s is O(10)).
// ---------------------------------------------------------------------------
#define SE_LD 68
__global__ __launch_bounds__(256)
void gemm_s_exp()
{
    extern __shared__ float sm_se[];
    float* Fs = sm_se;                 // [128][68]
    float* Gs = sm_se + 128 * SE_LD;   // [128][68]

    const int tid  = threadIdx.x;
    const int warp = tid >> 5;
    const int wm   = warp >> 2;        // 0..1
    const int wn   = warp & 3;         // 0..3
    const int bm   = blockIdx.y * 128;
    const int bn   = blockIdx.x * 128;
    const int b    = blockIdx.z;

    const float* F = g_f + (size_t)b * NPIX * DQ;
    const float* G = g_g + (size_t)b * NPIX * DQ;
    float* S = g_s + (size_t)b * NPIX * NPIX;

    #pragma unroll
    for (int l = 0; l < 8; l++) {
        int i = tid + l * 256;
        int r = i >> 4, c4 = i & 15;
        *reinterpret_cast<float4*>(&Fs[r * SE_LD + c4 * 4]) =
            *reinterpret_cast<const float4*>(&F[(size_t)(bm + r) * DQ + c4 * 4]);
        *reinterpret_cast<float4*>(&Gs[r * SE_LD + c4 * 4]) =
            *reinterpret_cast<const float4*>(&G[(size_t)(bn + r) * DQ + c4 * 4]);
    }
    __syncthreads();

    wmma::fragment<wmma::accumulator, 16, 16, 8, float> acc[4][2];
    #pragma unroll
    for (int mi = 0; mi < 4; mi++)
        #pragma unroll
        for (int ni = 0; ni < 2; ni++)
            wmma::fill_fragment(acc[mi][ni], 0.0f);

    #pragma unroll
    for (int kk = 0; kk < DQ; kk += 8) {
        wmma::fragment<wmma::matrix_a, 16, 16, 8, wmma::precision::tf32, wmma::row_major> af[4];
        wmma::fragment<wmma::matrix_b, 16, 16, 8, wmma::precision::tf32, wmma::col_major> bf[2];
        #pragma unroll
        for (int mi = 0; mi < 4; mi++) {
            wmma::load_matrix_sync(af[mi], &Fs[(wm * 64 + mi * 16) * SE_LD + kk], SE_LD);
            #pragma unroll
            for (int e = 0; e < af[mi].num_elements; e++)
                af[mi].x[e] = wmma::__float_to_tf32(af[mi].x[e]);
        }
        #pragma unroll
        for (int ni = 0; ni < 2; ni++) {
            wmma::load_matrix_sync(bf[ni], &Gs[(wn * 32 + ni * 16) * SE_LD + kk], SE_LD);
            #pragma unroll
            for (int e = 0; e < bf[ni].num_elements; e++)
                bf[ni].x[e] = wmma::__float_to_tf32(bf[ni].x[e]);
        }
        #pragma unroll
        for (int mi = 0; mi < 4; mi++)
            #pragma unroll
            for (int ni = 0; ni < 2; ni++)
                wmma::mma_sync(acc[mi][ni], af[mi], bf[ni], acc[mi][ni]);
    }

    const float LOG2E = 1.4426950408889634f;
    #pragma unroll
    for (int mi = 0; mi < 4; mi++)
        #pragma unroll
        for (int ni = 0; ni < 2; ni++) {
            #pragma unroll
            for (int e = 0; e < acc[mi][ni].num_elements; e++)
                acc[mi][ni].x[e] = exp2f(acc[mi][ni].x[e] * LOG2E);
            wmma::store_matrix_sync(
                &S[(size_t)(bm + wm * 64 + mi * 16) * NPIX + bn + wn * 32 + ni * 16],
                acc[mi][ni], NPIX, wmma::mem_row_major);
        }
}

// ---------------------------------------------------------------------------
// out = gamma * (P @ V) + x, where P = rownorm(exp(S)).
// M-tile 64, N = 512 (full), K-tile 32, 512 threads, 16 warps (warp tile 64x32).
// exp(S) read ONCE; row sums computed in-kernel from the A tiles.
// ---------------------------------------------------------------------------
#define PV_ALD 36
#define PV_BLD 520
#define PV_ABUF (64 * PV_ALD)       // 2304
#define PV_BBUF (32 * PV_BLD)       // 16640
#define PV_TILES (NPIX / 32)        // 128

__global__ __launch_bounds__(512, 1)
void gemm_pv(const float* __restrict__ x, const float* __restrict__ gam_p,
             float* __restrict__ out)
{
    extern __shared__ float sm_pv[];
    float* As     = sm_pv;                       // 2 * 64 * 36
    float* Bs     = sm_pv + 2 * PV_ABUF;         // 2 * 32 * 520  (reused as stage)
    float* rowsum = sm_pv + 2 * PV_ABUF + 2 * PV_BBUF;  // 64

    const int tid  = threadIdx.x;
    const int warp = tid >> 5;
    const int bm   = blockIdx.x * 64;
    const int b    = blockIdx.y;

    const float* S = g_s + (size_t)b * NPIX * NPIX;
    const float* V = g_v + (size_t)b * NPIX * CH;

    const int ar  = tid >> 3;
    const int ac4 = tid & 7;

    if (tid < 64) rowsum[tid] = 0.0f;

    // ---- preload tile 0 ----
    {
        cp_async16(&As[ar * PV_ALD + ac4 * 4],
                   &S[(size_t)(bm + ar) * NPIX + ac4 * 4]);
        #pragma unroll
        for (int l = 0; l < 8; l++) {
            int i = tid + l * 512;
            int r = i >> 7, c4 = i & 127;
            cp_async16(&Bs[r * PV_BLD + c4 * 4],
                       &V[(size_t)r * CH + c4 * 4]);
        }
        cp_commit();
    }
    cp_wait_all();
    __syncthreads();

    wmma::fragment<wmma::accumulator, 16, 16, 8, float> acc[4][2];
    #pragma unroll
    for (int mi = 0; mi < 4; mi++)
        #pragma unroll
        for (int ni = 0; ni < 2; ni++)
            wmma::fill_fragment(acc[mi][ni], 0.0f);

    for (int t = 0; t < PV_TILES; t++) {
        const int cur = t & 1;
        if (t + 1 < PV_TILES) {
            const int nxt = cur ^ 1;
            const int k0 = (t + 1) * 32;
            cp_async16(&As[nxt * PV_ABUF + ar * PV_ALD + ac4 * 4],
                       &S[(size_t)(bm + ar) * NPIX + k0 + ac4 * 4]);
            #pragma unroll
            for (int l = 0; l < 8; l++) {
                int i = tid + l * 512;
                int r = i >> 7, c4 = i & 127;
                cp_async16(&Bs[nxt * PV_BBUF + r * PV_BLD + c4 * 4],
                           &V[(size_t)(k0 + r) * CH + c4 * 4]);
            }
            cp_commit();
        }

        // row-sum contribution from this A tile (each thread owns 1 float4)
        {
            float4 a4 = *reinterpret_cast<float4*>(&As[cur * PV_ABUF + ar * PV_ALD + ac4 * 4]);
            float p = a4.x + a4.y + a4.z + a4.w;
            p += __shfl_xor_sync(0xFFFFFFFFu, p, 1);
            p += __shfl_xor_sync(0xFFFFFFFFu, p, 2);
            p += __shfl_xor_sync(0xFFFFFFFFu, p, 4);
            if ((tid & 7) == 0) rowsum[ar] += p;
        }

        #pragma unroll
        for (int kk = 0; kk < 32; kk += 8) {
            wmma::fragment<wmma::matrix_a, 16, 16, 8, wmma::precision::tf32, wmma::row_major> af[4];
            wmma::fragment<wmma::matrix_b, 16, 16, 8, wmma::precision::tf32, wmma::row_major> bf[2];
            #pragma unroll
            for (int mi = 0; mi < 4; mi++) {
                wmma::load_matrix_sync(af[mi], &As[cur * PV_ABUF + (mi * 16) * PV_ALD + kk], PV_ALD);
                #pragma unroll
                for (int e = 0; e < af[mi].num_elements; e++)
                    af[mi].x[e] = wmma::__float_to_tf32(af[mi].x[e]);
            }
            #pragma unroll
            for (int ni = 0; ni < 2; ni++) {
                wmma::load_matrix_sync(bf[ni], &Bs[cur * PV_BBUF + kk * PV_BLD + warp * 32 + ni * 16], PV_BLD);
                #pragma unroll
                for (int e = 0; e < bf[ni].num_elements; e++)
                    bf[ni].x[e] = wmma::__float_to_tf32(bf[ni].x[e]);
            }
            #pragma unroll
            for (int mi = 0; mi < 4; mi++)
                #pragma unroll
                for (int ni = 0; ni < 2; ni++)
                    wmma::mma_sync(acc[mi][ni], af[mi], bf[ni], acc[mi][ni]);
        }

        if (t + 1 < PV_TILES) {
            cp_wait_all();
            __syncthreads();
        }
    }

    // ---- epilogue: stage -> normalize -> gamma -> +x -> gmem ----
    __syncthreads();                    // all compute done; Bs free for staging
    float* stage = Bs;                  // 64 x 520
    #pragma unroll
    for (int mi = 0; mi < 4; mi++)
        #pragma unroll
        for (int ni = 0; ni < 2; ni++)
            wmma::store_matrix_sync(&stage[(mi * 16) * PV_BLD + warp * 32 + ni * 16],
                                    acc[mi][ni], PV_BLD, wmma::mem_row_major);
    __syncthreads();

    const float gam = gam_p[0];
    // 64 rows x 128 float4-cols = 8192 float4 -> 16 iterations of 512 threads
    #pragma unroll
    for (int l = 0; l < 16; l++) {
        int i = tid + l * 512;
        int r = i >> 7, c4 = i & 127;
        float4 s4 = *reinterpret_cast<float4*>(&stage[r * PV_BLD + c4 * 4]);
        const float sc = gam / rowsum[r];
        size_t gidx = ((size_t)b * NPIX + bm + r) * CH + c4 * 4;
        float4 x4 = *reinterpret_cast<const float4*>(&x[gidx]);
        float4 o;
        o.x = s4.x * sc + x4.x;
        o.y = s4.y * sc + x4.y;
        o.z = s4.z * sc + x4.z;
        o.w = s4.w * sc + x4.w;
        *reinterpret_cast<float4*>(&out[gidx]) = o;
    }
}

// ---------------------------------------------------------------------------
extern "C" void kernel_launch(void* const* d_in, const int* in_sizes, int n_in,
                              void* d_out, int out_size)
{
    const float* x     = (const float*)d_in[0];
    const float* wf    = (const float*)d_in[1];
    const float* wg    = (const float*)d_in[2];
    const float* wh    = (const float*)d_in[3];
    const float* gamma = (const float*)d_in[4];
    float* out = (float*)d_out;

    float *pf, *pg, *pv;
    cudaGetSymbolAddress((void**)&pf, g_f);
    cudaGetSymbolAddress((void**)&pg, g_g);
    cudaGetSymbolAddress((void**)&pv, g_v);

    const int SE_SMEM = 2 * 128 * SE_LD * 4;                       // 69632
    const int PV_SMEM = (2 * PV_ABUF + 2 * PV_BBUF + 64) * 4;      // 151808
    static bool attr_done = false;
    if (!attr_done) {
        cudaFuncSetAttribute(gemm_s_exp, cudaFuncAttributeMaxDynamicSharedMemorySize, SE_SMEM);
        cudaFuncSetAttribute(gemm_pv,    cudaFuncAttributeMaxDynamicSharedMemorySize, PV_SMEM);
        attr_done = true;
    }

    // f, g projections (small; FFMA path)
    gemm_proj<<<dim3(1, MTOT / 64), dim3(16, 16)>>>(x, wf, pf, MTOT, DQ, CH);
    gemm_proj<<<dim3(1, MTOT / 64), dim3(16, 16)>>>(x, wg, pg, MTOT, DQ, CH);

    // v = x @ Wh
    gemm_v<<<dim3(CH / 128, MTOT / 128), 256>>>(x, wh, pv);

    // exp(S) = exp(f @ g^T)
    gemm_s_exp<<<dim3(NPIX / 128, NPIX / 128, BATCH), 256, SE_SMEM>>>();

    // out = gamma * rownorm(exp(S)) @ V + x
    gemm_pv<<<dim3(NPIX / 64, BATCH), 512, PV_SMEM>>>(x, gamma, out);
}

// round 5
// speedup vs baseline: 3.2693x; 1.9804x over previous
#include <cuda_runtime.h>
#include <cuda_bf16.h>
#include <mma.h>
#include <math.h>
#include <stdint.h>

using namespace nvcuda;

#define BATCH 4
#define NPIX  4096
#define CH    512
#define DQ    64
#define MTOT  (BATCH*NPIX)

// Scratch (device globals: the sanctioned no-alloc workaround)
static __device__ float          g_f[BATCH * NPIX * DQ];
static __device__ float          g_g[BATCH * NPIX * DQ];
static __device__ __nv_bfloat16  g_vh[(size_t)MTOT * CH];          // 16 MB
static __device__ __nv_bfloat16  g_sh[(size_t)BATCH * NPIX * NPIX]; // 128 MB, exp(S) bf16

// ---------------------------------------------------------------------------
// cp.async helpers
// ---------------------------------------------------------------------------
__device__ __forceinline__ void cp_async16(void* smem_dst, const void* gmem_src) {
    uint32_t sa = (uint32_t)__cvta_generic_to_shared(smem_dst);
    asm volatile("cp.async.cg.shared.global [%0], [%1], 16;\n" :: "r"(sa), "l"(gmem_src));
}
__device__ __forceinline__ void cp_commit() {
    asm volatile("cp.async.commit_group;\n");
}
__device__ __forceinline__ void cp_wait_all() {
    asm volatile("cp.async.wait_group 0;\n");
}

__device__ __forceinline__ uint32_t pack_bf162(float lo, float hi) {
    __nv_bfloat162 h = __floats2bfloat162_rn(lo, hi);
    return *reinterpret_cast<uint32_t*>(&h);
}

// ---------------------------------------------------------------------------
// FFMA GEMM for the small f/g projections (N=64): C = A[M,K] @ B[K,64]
// ---------------------------------------------------------------------------
__global__ __launch_bounds__(256)
void gemm_proj(const float* __restrict__ A, const float* __restrict__ B,
               float* __restrict__ C, int M, int N, int K)
{
    __shared__ float As[64][33];
    __shared__ float Bs[32][64];

    const int tx = threadIdx.x, ty = threadIdx.y;
    const int tid = ty * 16 + tx;
    const int bm = blockIdx.y * 64;
    const int bn = blockIdx.x * 64;

    float acc[4][4] = {};

    for (int k0 = 0; k0 < K; k0 += 32) {
        #pragma unroll
        for (int l = 0; l < 8; l++) {
            int idx = tid + l * 256;
            int r = idx >> 5, c = idx & 31;
            As[r][c] = A[(size_t)(bm + r) * K + k0 + c];
        }
        #pragma unroll
        for (int l = 0; l < 8; l++) {
            int idx = tid + l * 256;
            int r = idx >> 6, c = idx & 63;
            Bs[r][c] = B[(size_t)(k0 + r) * N + bn + c];
        }
        __syncthreads();

        #pragma unroll
        for (int kk = 0; kk < 32; kk++) {
            float a[4], b[4];
            #pragma unroll
            for (int i = 0; i < 4; i++) a[i] = As[ty * 4 + i][kk];
            #pragma unroll
            for (int j = 0; j < 4; j++) b[j] = Bs[kk][tx * 4 + j];
            #pragma unroll
            for (int i = 0; i < 4; i++)
                #pragma unroll
                for (int j = 0; j < 4; j++)
                    acc[i][j] += a[i] * b[j];
        }
        __syncthreads();
    }

    #pragma unroll
    for (int i = 0; i < 4; i++)
        #pragma unroll
        for (int j = 0; j < 4; j++)
            C[(size_t)(bm + ty * 4 + i) * N + bn + tx * 4 + j] = acc[i][j];
}

// ---------------------------------------------------------------------------
// v = x @ Wh : TF32 GEMM, 128x128 tile, writes V in bf16 (per-warp staging).
// ---------------------------------------------------------------------------
__global__ __launch_bounds__(256)
void gemm_v(const float* __restrict__ A, const float* __restrict__ B,
            __nv_bfloat16* __restrict__ C)
{
    __shared__ float As[128][36];
    __shared__ float Bs[32][132];
    __shared__ float wscr[8][256];    // per-warp 16x16 stage

    const int tid  = threadIdx.x;
    const int warp = tid >> 5;
    const int lane = tid & 31;
    const int wm   = warp >> 2;
    const int wn   = warp & 3;
    const int bm   = blockIdx.y * 128;
    const int bn   = blockIdx.x * 128;

    wmma::fragment<wmma::accumulator, 16, 16, 8, float> acc[4][2];
    #pragma unroll
    for (int mi = 0; mi < 4; mi++)
        #pragma unroll
        for (int ni = 0; ni < 2; ni++)
            wmma::fill_fragment(acc[mi][ni], 0.0f);

    for (int k0 = 0; k0 < CH; k0 += 32) {
        #pragma unroll
        for (int l = 0; l < 4; l++) {
            int i = tid + l * 256;
            int r = i >> 3, c4 = i & 7;
            *reinterpret_cast<float4*>(&As[r][c4 * 4]) =
                *reinterpret_cast<const float4*>(&A[(size_t)(bm + r) * CH + k0 + c4 * 4]);
        }
        #pragma unroll
        for (int l = 0; l < 4; l++) {
            int i = tid + l * 256;
            int r = i >> 5, c4 = i & 31;
            *reinterpret_cast<float4*>(&Bs[r][c4 * 4]) =
                *reinterpret_cast<const float4*>(&B[(size_t)(k0 + r) * CH + bn + c4 * 4]);
        }
        __syncthreads();

        #pragma unroll
        for (int kk = 0; kk < 32; kk += 8) {
            wmma::fragment<wmma::matrix_a, 16, 16, 8, wmma::precision::tf32, wmma::row_major> af[4];
            wmma::fragment<wmma::matrix_b, 16, 16, 8, wmma::precision::tf32, wmma::row_major> bf[2];
            #pragma unroll
            for (int mi = 0; mi < 4; mi++) {
                wmma::load_matrix_sync(af[mi], &As[wm * 64 + mi * 16][kk], 36);
                #pragma unroll
                for (int e = 0; e < af[mi].num_elements; e++)
                    af[mi].x[e] = wmma::__float_to_tf32(af[mi].x[e]);
            }
            #pragma unroll
            for (int ni = 0; ni < 2; ni++) {
                wmma::load_matrix_sync(bf[ni], &Bs[kk][wn * 32 + ni * 16], 132);
                #pragma unroll
                for (int e = 0; e < bf[ni].num_elements; e++)
                    bf[ni].x[e] = wmma::__float_to_tf32(bf[ni].x[e]);
            }
            #pragma unroll
            for (int mi = 0; mi < 4; mi++)
                #pragma unroll
                for (int ni = 0; ni < 2; ni++)
                    wmma::mma_sync(acc[mi][ni], af[mi], bf[ni], acc[mi][ni]);
        }
        __syncthreads();
    }

    // bf16 epilogue via per-warp scratch
    const int srow = lane >> 1;
    const int shalf = lane & 1;
    #pragma unroll
    for (int mi = 0; mi < 4; mi++)
        #pragma unroll
        for (int ni = 0; ni < 2; ni++) {
            wmma::store_matrix_sync(&wscr[warp][0], acc[mi][ni], 16, wmma::mem_row_major);
            __syncwarp();
            const float* src = &wscr[warp][srow * 16 + shalf * 8];
            uint4 o;
            o.x = pack_bf162(src[0], src[1]);
            o.y = pack_bf162(src[2], src[3]);
            o.z = pack_bf162(src[4], src[5]);
            o.w = pack_bf162(src[6], src[7]);
            __nv_bfloat16* dst = &C[(size_t)(bm + wm * 64 + mi * 16 + srow) * CH
                                    + bn + wn * 32 + ni * 16 + shalf * 8];
            *reinterpret_cast<uint4*>(dst) = o;
            __syncwarp();
        }
}

// ---------------------------------------------------------------------------
// exp(S) = exp(f @ g^T), per batch. 128x128 tile, single K=64 pass.
// Writes UNNORMALIZED exp(s) as bf16 (softmax shift-invariant; s is O(10)).
// Dynamic smem: Fs[128][68] + Gs[128][68] = 69632 B; stage reuses it (128x132 f32).
// ---------------------------------------------------------------------------
#define SE_LD 68
#define SE_STG 132
__global__ __launch_bounds__(256)
void gemm_s_exp()
{
    extern __shared__ float sm_se[];
    float* Fs = sm_se;                 // [128][68]
    float* Gs = sm_se + 128 * SE_LD;   // [128][68]

    const int tid  = threadIdx.x;
    const int warp = tid >> 5;
    const int wm   = warp >> 2;        // 0..1
    const int wn   = warp & 3;         // 0..3
    const int bm   = blockIdx.y * 128;
    const int bn   = blockIdx.x * 128;
    const int b    = blockIdx.z;

    const float* F = g_f + (size_t)b * NPIX * DQ;
    const float* G = g_g + (size_t)b * NPIX * DQ;
    __nv_bfloat16* S = g_sh + (size_t)b * NPIX * NPIX;

    #pragma unroll
    for (int l = 0; l < 8; l++) {
        int i = tid + l * 256;
        int r = i >> 4, c4 = i & 15;
        *reinterpret_cast<float4*>(&Fs[r * SE_LD + c4 * 4]) =
            *reinterpret_cast<const float4*>(&F[(size_t)(bm + r) * DQ + c4 * 4]);
        *reinterpret_cast<float4*>(&Gs[r * SE_LD + c4 * 4]) =
            *reinterpret_cast<const float4*>(&G[(size_t)(bn + r) * DQ + c4 * 4]);
    }
    __syncthreads();

    wmma::fragment<wmma::accumulator, 16, 16, 8, float> acc[4][2];
    #pragma unroll
    for (int mi = 0; mi < 4; mi++)
        #pragma unroll
        for (int ni = 0; ni < 2; ni++)
            wmma::fill_fragment(acc[mi][ni], 0.0f);

    #pragma unroll
    for (int kk = 0; kk < DQ; kk += 8) {
        wmma::fragment<wmma::matrix_a, 16, 16, 8, wmma::precision::tf32, wmma::row_major> af[4];
        wmma::fragment<wmma::matrix_b, 16, 16, 8, wmma::precision::tf32, wmma::col_major> bf[2];
        #pragma unroll
        for (int mi = 0; mi < 4; mi++) {
            wmma::load_matrix_sync(af[mi], &Fs[(wm * 64 + mi * 16) * SE_LD + kk], SE_LD);
            #pragma unroll
            for (int e = 0; e < af[mi].num_elements; e++)
                af[mi].x[e] = wmma::__float_to_tf32(af[mi].x[e]);
        }
        #pragma unroll
        for (int ni = 0; ni < 2; ni++) {
            wmma::load_matrix_sync(bf[ni], &Gs[(wn * 32 + ni * 16) * SE_LD + kk], SE_LD);
            #pragma unroll
            for (int e = 0; e < bf[ni].num_elements; e++)
                bf[ni].x[e] = wmma::__float_to_tf32(bf[ni].x[e]);
        }
        #pragma unroll
        for (int mi = 0; mi < 4; mi++)
            #pragma unroll
            for (int ni = 0; ni < 2; ni++)
                wmma::mma_sync(acc[mi][ni], af[mi], bf[ni], acc[mi][ni]);
    }

    // exp in fragments, stage fp32 tile, convert+store bf16
    const float LOG2E = 1.4426950408889634f;
    #pragma unroll
    for (int mi = 0; mi < 4; mi++)
        #pragma unroll
        for (int ni = 0; ni < 2; ni++)
            #pragma unroll
            for (int e = 0; e < acc[mi][ni].num_elements; e++)
                acc[mi][ni].x[e] = exp2f(acc[mi][ni].x[e] * LOG2E);

    __syncthreads();                // F/G tiles fully consumed -> reuse as stage
    float* stage = sm_se;           // [128][132]
    #pragma unroll
    for (int mi = 0; mi < 4; mi++)
        #pragma unroll
        for (int ni = 0; ni < 2; ni++)
            wmma::store_matrix_sync(&stage[(wm * 64 + mi * 16) * SE_STG + wn * 32 + ni * 16],
                                    acc[mi][ni], SE_STG, wmma::mem_row_major);
    __syncthreads();

    // 128 rows x 16 chunks of 8 bf16 = 2048 chunks, 8 per thread
    #pragma unroll
    for (int l = 0; l < 8; l++) {
        int i = tid + l * 256;
        int r = i >> 4, c = i & 15;
        const float* src = &stage[r * SE_STG + c * 8];
        uint4 o;
        o.x = pack_bf162(src[0], src[1]);
        o.y = pack_bf162(src[2], src[3]);
        o.z = pack_bf162(src[4], src[5]);
        o.w = pack_bf162(src[6], src[7]);
        *reinterpret_cast<uint4*>(&S[(size_t)(bm + r) * NPIX + bn + c * 8]) = o;
    }
}

// ---------------------------------------------------------------------------
// out = gamma * (P @ V) + x, where P = rownorm(exp(S)), all bf16 inputs.
// M-tile 64, N = 512 (full), K-tile 64, 512 threads, 16 warps (warp 64x32).
// bf16 m16n16k16 wmma. Row sums computed from the bf16 A tiles in-kernel.
// Dynamic smem: As 2*64*72*2=18432, Bs 2*64*520*2=133120, rowsum 256 -> 151808B
// ---------------------------------------------------------------------------
#define PV_ALD 72
#define PV_BLD 520
#define PV_ABUF (64 * PV_ALD)       // bf16 elems per A buffer (4608)
#define PV_BBUF (64 * PV_BLD)       // bf16 elems per B buffer (33280)
#define PV_TILES (NPIX / 64)        // 64

__global__ __launch_bounds__(512, 1)
void gemm_pv(const float* __restrict__ x, const float* __restrict__ gam_p,
             float* __restrict__ out)
{
    extern __shared__ __nv_bfloat16 sm_pv[];
    __nv_bfloat16* As = sm_pv;                        // 2 * 4608
    __nv_bfloat16* Bs = sm_pv + 2 * PV_ABUF;          // 2 * 33280 (reused as f32 stage)
    float* rowsum = reinterpret_cast<float*>(sm_pv + 2 * PV_ABUF + 2 * PV_BBUF); // 64

    const int tid  = threadIdx.x;
    const int warp = tid >> 5;
    const int bm   = blockIdx.x * 64;
    const int b    = blockIdx.y;

    const __nv_bfloat16* S = g_sh + (size_t)b * NPIX * NPIX;
    const __nv_bfloat16* V = g_vh + (size_t)b * NPIX * CH;

    // A-tile: 64 rows x 8 chunks of 8 bf16 = 512 chunks, 1/thread
    const int ar  = tid >> 3;
    const int ac8 = tid & 7;

    if (tid < 64) rowsum[tid] = 0.0f;

    // ---- preload tile 0 ----
    {
        cp_async16(&As[ar * PV_ALD + ac8 * 8], &S[(size_t)(bm + ar) * NPIX + ac8 * 8]);
        #pragma unroll
        for (int l = 0; l < 8; l++) {
            int i = tid + l * 512;
            int r = i >> 6, c8 = i & 63;
            cp_async16(&Bs[r * PV_BLD + c8 * 8], &V[(size_t)r * CH + c8 * 8]);
        }
        cp_commit();
    }
    cp_wait_all();
    __syncthreads();

    wmma::fragment<wmma::accumulator, 16, 16, 16, float> acc[4][2];
    #pragma unroll
    for (int mi = 0; mi < 4; mi++)
        #pragma unroll
        for (int ni = 0; ni < 2; ni++)
            wmma::fill_fragment(acc[mi][ni], 0.0f);

    for (int t = 0; t < PV_TILES; t++) {
        const int cur = t & 1;
        if (t + 1 < PV_TILES) {
            const int nxt = cur ^ 1;
            const int k0 = (t + 1) * 64;
            cp_async16(&As[nxt * PV_ABUF + ar * PV_ALD + ac8 * 8],
                       &S[(size_t)(bm + ar) * NPIX + k0 + ac8 * 8]);
            #pragma unroll
            for (int l = 0; l < 8; l++) {
                int i = tid + l * 512;
                int r = i >> 6, c8 = i & 63;
                cp_async16(&Bs[nxt * PV_BBUF + r * PV_BLD + c8 * 8],
                           &V[(size_t)(k0 + r) * CH + c8 * 8]);
            }
            cp_commit();
        }

        // row-sum from the bf16 A tile (each thread owns one 8-elem chunk)
        {
            const __nv_bfloat162* a2 = reinterpret_cast<const __nv_bfloat162*>(
                &As[cur * PV_ABUF + ar * PV_ALD + ac8 * 8]);
            float p = 0.0f;
            #pragma unroll
            for (int q = 0; q < 4; q++) {
                float2 f2 = __bfloat1622float2(a2[q]);
                p += f2.x + f2.y;
            }
            p += __shfl_xor_sync(0xFFFFFFFFu, p, 1);
            p += __shfl_xor_sync(0xFFFFFFFFu, p, 2);
            p += __shfl_xor_sync(0xFFFFFFFFu, p, 4);
            if ((tid & 7) == 0) rowsum[ar] += p;
        }

        // MMA on current buffer: K = 64 in 4 steps of 16
        #pragma unroll
        for (int kk = 0; kk < 64; kk += 16) {
            wmma::fragment<wmma::matrix_a, 16, 16, 16, __nv_bfloat16, wmma::row_major> af[4];
            wmma::fragment<wmma::matrix_b, 16, 16, 16, __nv_bfloat16, wmma::row_major> bf[2];
            #pragma unroll
            for (int mi = 0; mi < 4; mi++)
                wmma::load_matrix_sync(af[mi], &As[cur * PV_ABUF + (mi * 16) * PV_ALD + kk], PV_ALD);
            #pragma unroll
            for (int ni = 0; ni < 2; ni++)
                wmma::load_matrix_sync(bf[ni], &Bs[cur * PV_BBUF + kk * PV_BLD + warp * 32 + ni * 16], PV_BLD);
            #pragma unroll
            for (int mi = 0; mi < 4; mi++)
                #pragma unroll
                for (int ni = 0; ni < 2; ni++)
                    wmma::mma_sync(acc[mi][ni], af[mi], bf[ni], acc[mi][ni]);
        }

        if (t + 1 < PV_TILES) {
            cp_wait_all();
            __syncthreads();
        }
    }

    // ---- epilogue: stage (f32, reuse Bs) -> normalize -> gamma -> +x ----
    __syncthreads();
    float* stage = reinterpret_cast<float*>(Bs);   // 64 x 520 f32 = 133120 B (fits)
    #pragma unroll
    for (int mi = 0; mi < 4; mi++)
        #pragma unroll
        for (int ni = 0; ni < 2; ni++)
            wmma::store_matrix_sync(&stage[(mi * 16) * PV_BLD + warp * 32 + ni * 16],
                                    acc[mi][ni], PV_BLD, wmma::mem_row_major);
    __syncthreads();

    const float gam = gam_p[0];
    // 64 rows x 128 float4-cols = 8192 float4 -> 16 iterations of 512 threads
    #pragma unroll
    for (int l = 0; l < 16; l++) {
        int i = tid + l * 512;
        int r = i >> 7, c4 = i & 127;
        float4 s4 = *reinterpret_cast<float4*>(&stage[r * PV_BLD + c4 * 4]);
        const float sc = gam / rowsum[r];
        size_t gidx = ((size_t)b * NPIX + bm + r) * CH + c4 * 4;
        float4 x4 = *reinterpret_cast<const float4*>(&x[gidx]);
        float4 o;
        o.x = s4.x * sc + x4.x;
        o.y = s4.y * sc + x4.y;
        o.z = s4.z * sc + x4.z;
        o.w = s4.w * sc + x4.w;
        *reinterpret_cast<float4*>(&out[gidx]) = o;
    }
}

// ---------------------------------------------------------------------------
extern "C" void kernel_launch(void* const* d_in, const int* in_sizes, int n_in,
                              void* d_out, int out_size)
{
    const float* x     = (const float*)d_in[0];
    const float* wf    = (const float*)d_in[1];
    const float* wg    = (const float*)d_in[2];
    const float* wh    = (const float*)d_in[3];
    const float* gamma = (const float*)d_in[4];
    float* out = (float*)d_out;

    float *pf, *pg;
    __nv_bfloat16* pvh;
    cudaGetSymbolAddress((void**)&pf,  g_f);
    cudaGetSymbolAddress((void**)&pg,  g_g);
    cudaGetSymbolAddress((void**)&pvh, g_vh);

    const int SE_SMEM = 2 * 128 * SE_LD * 4;                          // 69632
    const int PV_SMEM = (2 * PV_ABUF + 2 * PV_BBUF) * 2 + 64 * 4;     // 151808
    static bool attr_done = false;
    if (!attr_done) {
        cudaFuncSetAttribute(gemm_s_exp, cudaFuncAttributeMaxDynamicSharedMemorySize, SE_SMEM);
        cudaFuncSetAttribute(gemm_pv,    cudaFuncAttributeMaxDynamicSharedMemorySize, PV_SMEM);
        attr_done = true;
    }

    // f, g projections (small; FFMA path)
    gemm_proj<<<dim3(1, MTOT / 64), dim3(16, 16)>>>(x, wf, pf, MTOT, DQ, CH);
    gemm_proj<<<dim3(1, MTOT / 64), dim3(16, 16)>>>(x, wg, pg, MTOT, DQ, CH);

    // v = x @ Wh  (bf16 output)
    gemm_v<<<dim3(CH / 128, MTOT / 128), 256>>>(x, wh, pvh);

    // exp(S) = exp(f @ g^T)  (bf16 output)
    gemm_s_exp<<<dim3(NPIX / 128, NPIX / 128, BATCH), 256, SE_SMEM>>>();

    // out = gamma * rownorm(exp(S)) @ V + x
    gemm_pv<<<dim3(NPIX / 64, BATCH), 512, PV_SMEM>>>(x, gamma, out);
}